// round 1
// baseline (speedup 1.0000x reference)
#include <cuda_runtime.h>
#include <cstdint>

#define NG    1000
#define NODES 100
#define EDGES 1600
#define NTOT  100000
#define ETOT  1600000
#define HID   128
#define KTOP  40

// ---------------- scratch (device globals; no runtime allocation) ----------
__device__ float g_T [(size_t)NTOT * HID];
__device__ float g_X0[(size_t)NTOT * HID];
__device__ float g_X1[(size_t)NTOT * HID];
__device__ float g_X2[(size_t)NTOT * HID];
__device__ int   g_off [NG * 101];
__device__ int   g_srcl[ETOT];
__device__ float g_normv[ETOT];

// ---------------- helpers ---------------------------------------------------
__device__ __forceinline__ float acc_tanh(float x) {
    // robust tanh independent of fast-math mapping of tanhf
    float xc = fminf(fmaxf(x, -10.f), 10.f);
    float e  = __expf(2.f * xc);
    return (e - 1.f) / (e + 1.f);
}

__device__ __forceinline__ unsigned long long pk2(float x) {
    unsigned long long r;
    int xi = __float_as_int(x);
    asm("mov.b64 %0, {%1, %1};" : "=l"(r) : "r"(xi));
    return r;
}
__device__ __forceinline__ void ffma2(unsigned long long& d,
                                      unsigned long long a,
                                      unsigned long long b) {
    asm("fma.rn.f32x2 %0, %1, %2, %3;" : "=l"(d) : "l"(a), "l"(b), "l"(d));
}

// ---------------- kernel 1: deterministic per-graph CSR --------------------
__global__ void __launch_bounds__(256) build_csr(const int* __restrict__ ei)
{
    __shared__ int   sdst[EDGES];
    __shared__ int   ssrc[EDGES];
    __shared__ int   deg[NODES];
    __shared__ float dinv[NODES];
    __shared__ int   offs[NODES + 1];

    const int g = blockIdx.x, tid = threadIdx.x;
    const int base = g * NODES;
    const int* srce = ei + (size_t)g * EDGES;
    const int* dste = ei + (size_t)ETOT + (size_t)g * EDGES;

    if (tid < NODES) deg[tid] = 0;
    __syncthreads();

    for (int e = tid; e < EDGES; e += 256) {
        int s = srce[e] - base;
        int d = dste[e] - base;
        ssrc[e] = s;
        sdst[e] = d;
        atomicAdd(&deg[d], 1);
    }
    __syncthreads();

    if (tid < NODES)
        dinv[tid] = deg[tid] > 0 ? rsqrtf((float)deg[tid]) : 0.f;
    if (tid == 0) {
        int acc = 0;
        for (int i = 0; i < NODES; i++) { offs[i] = acc; acc += deg[i]; }
        offs[NODES] = acc;
    }
    __syncthreads();

    if (tid <= NODES) g_off[g * 101 + tid] = offs[tid];

    // deterministic ordered fill: warp per row, ballot-compaction
    const int lane = tid & 31, warp = tid >> 5;
    const size_t gb = (size_t)g * EDGES;
    for (int d = warp; d < NODES; d += 8) {
        int pos = offs[d];
        float dd = dinv[d];
        for (int eb = 0; eb < EDGES; eb += 32) {
            int e = eb + lane;
            bool m = (sdst[e] == d);
            unsigned mask = __ballot_sync(0xffffffffu, m);
            if (m) {
                int idx = pos + __popc(mask & ((1u << lane) - 1));
                int s = ssrc[e];
                g_srcl [gb + idx] = s;
                g_normv[gb + idx] = dinv[s] * dd;
            }
            pos += __popc(mask);
        }
    }
}

// ---------------- kernel 2: SGEMM  C[M,128] = H[M,K] @ W[K,128] -------------
// FUSE=1: H row i = [ z_table[z[i]] | x[i] ]  (K=256, no H0 materialization)
template <int FUSE, int K>
__global__ void __launch_bounds__(256, 2) gemm_k(
    const float* __restrict__ A, const int* __restrict__ z,
    const float* __restrict__ ztab, const float* __restrict__ xin,
    const float* __restrict__ B, float* __restrict__ C, int M)
{
    __shared__ __align__(16) float As[8][128];
    __shared__ __align__(16) float Bs[8][128];

    const int tid  = threadIdx.x;
    const int row0 = blockIdx.x * 128;
    const int a_row = tid >> 1, a_k4 = (tid & 1) * 4;
    const int b_k = tid >> 5, b_c = (tid & 31) << 2;
    const int gr = row0 + a_row;
    const bool rv = gr < M;
    int zi = 0;
    if (FUSE && rv) zi = z[gr];

    auto loadA = [&](int k0) -> float4 {
        if (!rv) return make_float4(0.f, 0.f, 0.f, 0.f);
        int kk = k0 + a_k4;
        const float* p;
        if (FUSE)
            p = (kk < 128) ? (ztab + (size_t)zi * 128 + kk)
                           : (xin + (size_t)gr * 128 + (kk - 128));
        else
            p = A + (size_t)gr * K + kk;
        return *(const float4*)p;
    };

    float4 an = loadA(0);
    float4 bn = *(const float4*)(B + (size_t)b_k * 128 + b_c);

    unsigned long long acc2[8][4];
#pragma unroll
    for (int i = 0; i < 8; i++)
#pragma unroll
        for (int p = 0; p < 4; p++) acc2[i][p] = 0ull;

    const int tr = (tid >> 4) << 3, tc = (tid & 15) << 3;

#pragma unroll 1
    for (int k0 = 0; k0 < K; k0 += 8) {
        As[a_k4 + 0][a_row] = an.x;
        As[a_k4 + 1][a_row] = an.y;
        As[a_k4 + 2][a_row] = an.z;
        As[a_k4 + 3][a_row] = an.w;
        *(float4*)&Bs[b_k][b_c] = bn;
        __syncthreads();

        if (k0 + 8 < K) {
            an = loadA(k0 + 8);
            bn = *(const float4*)(B + (size_t)(k0 + 8 + b_k) * 128 + b_c);
        }

#pragma unroll
        for (int kk = 0; kk < 8; kk++) {
            float ra[8];
            *(float4*)(ra)     = *(const float4*)&As[kk][tr];
            *(float4*)(ra + 4) = *(const float4*)&As[kk][tr + 4];
            ulonglong2 q0 = *(const ulonglong2*)&Bs[kk][tc];
            ulonglong2 q1 = *(const ulonglong2*)&Bs[kk][tc + 4];
            unsigned long long rb0 = q0.x, rb1 = q0.y, rb2v = q1.x, rb3 = q1.y;
#pragma unroll
            for (int i = 0; i < 8; i++) {
                unsigned long long ai = pk2(ra[i]);
                ffma2(acc2[i][0], ai, rb0);
                ffma2(acc2[i][1], ai, rb1);
                ffma2(acc2[i][2], ai, rb2v);
                ffma2(acc2[i][3], ai, rb3);
            }
        }
        __syncthreads();
    }

    union U { unsigned long long u; float2 f; };
#pragma unroll
    for (int i = 0; i < 8; i++) {
        int r = row0 + tr + i;
        if (r < M) {
            U u0, u1, u2, u3;
            u0.u = acc2[i][0]; u1.u = acc2[i][1];
            u2.u = acc2[i][2]; u3.u = acc2[i][3];
            *(float4*)(C + (size_t)r * 128 + tc)     = make_float4(u0.f.x, u0.f.y, u1.f.x, u1.f.y);
            *(float4*)(C + (size_t)r * 128 + tc + 4) = make_float4(u2.f.x, u2.f.y, u3.f.x, u3.f.y);
        }
    }
}

// ---------------- kernel 3: X = tanh(A_norm @ T + b) per graph --------------
__global__ void __launch_bounds__(256) agg_tanh(
    const float* __restrict__ T, const float* __restrict__ bias,
    float* __restrict__ Xout)
{
    extern __shared__ float Ts[]; // [100][128]
    const int g = blockIdx.x, tid = threadIdx.x;
    const float* Tg = T + (size_t)g * NODES * HID;

    for (int t = tid; t < NODES * HID / 4; t += 256)
        ((float4*)Ts)[t] = ((const float4*)Tg)[t];
    __syncthreads();

    const int lane = tid & 31, warp = tid >> 5;
    const float4 bv = *(const float4*)(bias + lane * 4);
    const int*   srcp = g_srcl + (size_t)g * EDGES;
    const float* nvp  = g_normv + (size_t)g * EDGES;
    const int*   offp = g_off + g * 101;

    for (int d = warp; d < NODES; d += 8) {
        int e0 = offp[d], e1 = offp[d + 1];
        float4 acc = make_float4(0.f, 0.f, 0.f, 0.f);
        for (int e = e0; e < e1; e++) {
            int s = srcp[e];
            float w = nvp[e];
            float4 tv = *(const float4*)&Ts[s * HID + lane * 4];
            acc.x += w * tv.x; acc.y += w * tv.y;
            acc.z += w * tv.z; acc.w += w * tv.w;
        }
        float4 o;
        o.x = acc_tanh(acc.x + bv.x);
        o.y = acc_tanh(acc.y + bv.y);
        o.z = acc_tanh(acc.z + bv.z);
        o.w = acc_tanh(acc.w + bv.w);
        *(float4*)(Xout + ((size_t)g * NODES + d) * HID + lane * 4) = o;
    }
}

// ---------------- kernel 4: layer3 + sort-pool + conv + MLP -----------------
#define FINAL_SMEM_FLOATS 38860
__global__ void __launch_bounds__(256) final_k(
    const float* __restrict__ W3,  const float* __restrict__ b3,
    const float* __restrict__ cw1, const float* __restrict__ cb1,
    const float* __restrict__ cw2, const float* __restrict__ cb2,
    const float* __restrict__ mW1, const float* __restrict__ mb1,
    const float* __restrict__ mW2, const float* __restrict__ mb2,
    float* __restrict__ out)
{
    extern __shared__ float sm[];
    float* X2s  = sm;                // 100*129 (padded stride vs bank conflict)
    float* cw1s = X2s + 100 * 129;   // 6160
    float* feat = cw1s + 6160;       // 40*385
    float* cw2s = feat + 40 * 385;   // 2560
    float* t3   = cw2s + 2560;       // 100
    float* x3   = t3 + 100;          // 100
    float* y1   = x3 + 100;          // 640
    float* mmp  = y1 + 640;          // 320
    float* flat = mmp + 320;         // 512
    float* rr   = flat + 512;        // 128
    int*   topi = (int*)(rr + 128);  // 40

    const int g = blockIdx.x, tid = threadIdx.x;
    const float* X2g = g_X2 + (size_t)g * NODES * HID;

    for (int t = tid; t < NODES * HID; t += 256) {
        int i = t >> 7, d = t & 127;
        X2s[i * 129 + d] = X2g[t];
    }
    for (int t = tid; t < 16 * 385; t += 256) cw1s[t] = cw1[t];
    for (int t = tid; t < 2560; t += 256)     cw2s[t] = cw2[t];
    __syncthreads();

    // ---- layer 3: t3 = X2 @ W3 --------------------------------------------
    if (tid < NODES) {
        float a = 0.f;
#pragma unroll 8
        for (int k = 0; k < HID; k++) a += X2s[tid * 129 + k] * W3[k];
        t3[tid] = a;
    }
    __syncthreads();

    // ---- x3 = tanh(A @ t3 + b3) --------------------------------------------
    if (tid < NODES) {
        const int*   offp = g_off + g * 101;
        const int*   srcp = g_srcl + (size_t)g * EDGES;
        const float* nvp  = g_normv + (size_t)g * EDGES;
        float a = 0.f;
        int e1 = offp[tid + 1];
        for (int e = offp[tid]; e < e1; e++) a += nvp[e] * t3[srcp[e]];
        x3[tid] = acc_tanh(a + b3[0]);
    }
    __syncthreads();

    // ---- stable descending rank (matches jnp.argsort(-v) tie-break) --------
    if (tid < NODES) {
        float v = x3[tid];
        int r = 0;
        for (int j = 0; j < NODES; j++) {
            float u = x3[j];
            r += (u > v) || (u == v && j < tid);
        }
        if (r < KTOP) topi[r] = tid;
    }
    __syncthreads();

    // ---- gather feat rows of top-K nodes -----------------------------------
    for (int t = tid; t < KTOP * HID; t += 256) {
        int k = t >> 7, d = t & 127;
        int node = topi[k];
        size_t gbase = ((size_t)g * NODES + node) * HID;
        feat[k * 385 + d]       = g_X0[gbase + d];
        feat[k * 385 + 128 + d] = g_X1[gbase + d];
        feat[k * 385 + 256 + d] = X2s[node * 129 + d];
    }
    if (tid < KTOP) feat[tid * 385 + 384] = x3[topi[tid]];
    __syncthreads();

    // ---- conv1 (stride 385) + relu ------------------------------------------
    for (int o = tid; o < 640; o += 256) {
        int c = o & 15, kp = o >> 4;
        float a = cb1[c];
        const float* wr = cw1s + c * 385;
        const float* fr = feat + kp * 385;
#pragma unroll 5
        for (int d = 0; d < 385; d++) a += wr[d] * fr[d];
        y1[c * 40 + kp] = fmaxf(a, 0.f);
    }
    __syncthreads();

    // ---- maxpool(2,2) -------------------------------------------------------
    for (int t = tid; t < 320; t += 256) {
        int c = t / 20, p = t % 20;
        mmp[t] = fmaxf(y1[c * 40 + 2 * p], y1[c * 40 + 2 * p + 1]);
    }
    __syncthreads();

    // ---- conv2 (16->32, k=5) + relu -----------------------------------------
    for (int t = tid; t < 512; t += 256) {
        int o2 = t >> 4, p = t & 15;
        float a = cb2[o2];
#pragma unroll
        for (int c = 0; c < 16; c++)
#pragma unroll
            for (int u = 0; u < 5; u++)
                a += cw2s[(o2 * 16 + c) * 5 + u] * mmp[c * 20 + p + u];
        flat[t] = fmaxf(a, 0.f);
    }
    __syncthreads();

    // ---- mlp1 ---------------------------------------------------------------
    if (tid < 128) {
        float a = mb1[tid];
#pragma unroll 8
        for (int i = 0; i < 512; i++) a += flat[i] * mW1[i * 128 + tid];
        rr[tid] = fmaxf(a, 0.f);
    }
    __syncthreads();

    // ---- mlp2 + write -------------------------------------------------------
    if (tid < 32) {
        float s = 0.f;
#pragma unroll
        for (int q = 0; q < 4; q++) s += rr[tid + 32 * q] * mW2[tid + 32 * q];
        for (int off2 = 16; off2 > 0; off2 >>= 1)
            s += __shfl_down_sync(0xffffffffu, s, off2);
        if (tid == 0) out[g] = s + mb2[0];
    }
}

// ---------------- host ------------------------------------------------------
extern "C" void kernel_launch(void* const* d_in, const int* in_sizes, int n_in,
                              void* d_out, int out_size)
{
    const float* x    = (const float*)d_in[0];
    const int*   z    = (const int*)  d_in[1];
    const int*   ei   = (const int*)  d_in[2];
    const float* ztab = (const float*)d_in[4];
    const float* W0   = (const float*)d_in[5];
    const float* b0   = (const float*)d_in[6];
    const float* W1   = (const float*)d_in[7];
    const float* b1   = (const float*)d_in[8];
    const float* W2   = (const float*)d_in[9];
    const float* b2   = (const float*)d_in[10];
    const float* W3   = (const float*)d_in[11];
    const float* b3   = (const float*)d_in[12];
    const float* cw1  = (const float*)d_in[13];
    const float* cb1  = (const float*)d_in[14];
    const float* cw2  = (const float*)d_in[15];
    const float* cb2  = (const float*)d_in[16];
    const float* mW1  = (const float*)d_in[17];
    const float* mb1  = (const float*)d_in[18];
    const float* mW2  = (const float*)d_in[19];
    const float* mb2  = (const float*)d_in[20];
    float* out = (float*)d_out;

    float *T, *X0, *X1, *X2;
    cudaGetSymbolAddress((void**)&T,  g_T);
    cudaGetSymbolAddress((void**)&X0, g_X0);
    cudaGetSymbolAddress((void**)&X1, g_X1);
    cudaGetSymbolAddress((void**)&X2, g_X2);

    cudaFuncSetAttribute(agg_tanh, cudaFuncAttributeMaxDynamicSharedMemorySize, 64 * 1024);
    cudaFuncSetAttribute(final_k,  cudaFuncAttributeMaxDynamicSharedMemorySize, 160 * 1024);

    const int GEMM_GRID = (NTOT + 127) / 128;
    const int AGG_SMEM  = NODES * HID * (int)sizeof(float); // 51200

    build_csr<<<NG, 256>>>(ei);

    gemm_k<1, 256><<<GEMM_GRID, 256>>>(nullptr, z, ztab, x, W0, T, NTOT);
    agg_tanh<<<NG, 256, AGG_SMEM>>>(T, b0, X0);

    gemm_k<0, 128><<<GEMM_GRID, 256>>>(X0, nullptr, nullptr, nullptr, W1, T, NTOT);
    agg_tanh<<<NG, 256, AGG_SMEM>>>(T, b1, X1);

    gemm_k<0, 128><<<GEMM_GRID, 256>>>(X1, nullptr, nullptr, nullptr, W2, T, NTOT);
    agg_tanh<<<NG, 256, AGG_SMEM>>>(T, b2, X2);

    final_k<<<NG, 256, FINAL_SMEM_FLOATS * 4>>>(W3, b3, cw1, cb1, cw2, cb2,
                                                mW1, mb1, mW2, mb2, out);
}